// round 7
// baseline (speedup 1.0000x reference)
#include <cuda_runtime.h>
#include <math.h>
#include <float.h>

#define OUTD    12
#define N_VOX   1728              // 12*12*12
#define N_ROIS  128
#define N_PTS   160000
#define NCH     64
#define KMAX    64                // cap on points per (roi,voxel); fallback handles overflow
#define NRV     (N_ROIS * N_VOX)  // 221184 = 864 * 256

static_assert(N_PTS % 256 == 0, "exact build grid");
static_assert(NRV % 256 == 0, "exact pool grid");

// Scratch (__device__ globals = sanctioned scratch; zero-initialized at load).
// d_count is self-cleaned by pool_kernel each run -> invariant holds across replays.
__device__ int d_count[NRV];
__device__ __align__(16) int d_list[NRV * KMAX];   // 16B align for int4 loads

// ---------------------------------------------------------------------------
// Kernel 1: one thread per point, warp-uniform loop over all 128 ROIs
// (params staged in smem, broadcast LDS.128). R4 form exactly — measured
// fastest (9.7us). No zero-fill here: keeps d_count/d_list L2-hot for pool.
// ---------------------------------------------------------------------------
__global__ __launch_bounds__(256) void build_lists_kernel(
    const float* __restrict__ rois, const float* __restrict__ pts)
{
    __shared__ float4 sA[N_ROIS];  // {cx, cy, r2_margin, cz}
    __shared__ float4 sB[N_ROIS];  // {cosa, sina, hdx, hdy}
    __shared__ float4 sC[N_ROIS];  // {hdz, vx, vy, vz}

    int t = threadIdx.x;
    if (t < N_ROIS) {
        const float* R = rois + t * 7;
        float cx = R[0], cy = R[1], cz = R[2];
        float dx = R[3], dy = R[4], dz = R[5];
        float ry = R[6];
        float hdx = dx * 0.5f, hdy = dy * 0.5f, hdz = dz * 0.5f;
        float r2  = (hdx * hdx + hdy * hdy) * 1.0002f + 1e-6f;  // conservative
        float ca  = cosf(-ry), sa = sinf(-ry);
        sA[t] = make_float4(cx, cy, r2, cz);
        sB[t] = make_float4(ca, sa, hdx, hdy);
        sC[t] = make_float4(hdz, dx / (float)OUTD, dy / (float)OUTD, dz / (float)OUTD);
    }
    __syncthreads();

    int p = blockIdx.x * blockDim.x + t;      // always < N_PTS (exact grid)
    float px = pts[3 * p + 0];
    float py = pts[3 * p + 1];
    float pz = pts[3 * p + 2];

    #pragma unroll 4
    for (int r = 0; r < N_ROIS; r++) {
        float4 A = sA[r];                     // broadcast LDS.128 (uniform r)
        float sx = px - A.x;
        float sy = py - A.y;
        float d2 = sx * sx + sy * sy;
        if (d2 > A.z) continue;               // ~99.8% rejected here

        float sz = pz - A.w;
        float4 B = sB[r];
        float4 C = sC[r];
        float lx = sx * B.x - sy * B.y;       // rotate into roi frame (angle = -ry)
        float ly = sx * B.y + sy * B.x;
        bool in_box = (lx > -B.z) && (lx < B.z) &&
                      (ly > -B.w) && (ly < B.w) &&
                      (fabsf(sz - C.x) <= C.x);
        if (!in_box) continue;

        int xi = min(OUTD - 1, max(0, (int)floorf((lx + B.z) / C.y)));
        int yi = min(OUTD - 1, max(0, (int)floorf((ly + B.w) / C.z)));
        int zi = min(OUTD - 1, max(0, (int)floorf(sz / C.w)));
        int rv = r * N_VOX + xi * (OUTD * OUTD) + yi * OUTD + zi;
        int c = atomicAdd(&d_count[rv], 1);
        if (c < KMAX) d_list[rv * KMAX + c] = p;
    }
}

// ---------------------------------------------------------------------------
// Kernel 2: block = 256 voxels, one wave (6 blocks/SM). Coalesced count scan
// into smem (+ self-clean of dirty entries), ballot-compaction of non-empty
// voxels, pipeline prefetch of first queue entries, THEN zero-fill of empty
// voxels in PAIRS (both-empty -> single STG.128/lane covering 512B = two
// voxel rows; ~85% of pairs). Queue processed with 2-deep pipeline.
// ---------------------------------------------------------------------------
__global__ __launch_bounds__(256, 6) void pool_kernel(
    const float* __restrict__ rois, const float* __restrict__ pts,
    const float* __restrict__ feat, float* __restrict__ out)
{
    __shared__ int sCnt[256];
    __shared__ int sQ[256];
    __shared__ int sQn;

    int t    = threadIdx.x;
    int lane = t & 31;
    int wid  = t >> 5;
    int vblock = blockIdx.x << 8;             // first voxel of this block

    int c = d_count[vblock + t];              // coalesced 1KB burst (L2-hot)
    sCnt[t] = c;
    if (c) d_count[vblock + t] = 0;           // self-clean only dirty entries
    if (t == 0) sQn = 0;
    __syncthreads();

    // Ballot-compact non-empty local voxel ids into sQ.
    unsigned m = __ballot_sync(0xffffffffu, c > 0);
    int base = 0;
    if (lane == 0 && m) base = atomicAdd(&sQn, __popc(m));
    base = __shfl_sync(0xffffffffu, base, 0);
    if (c > 0) sQ[base + __popc(m & ((1u << lane) - 1u))] = t;
    __syncthreads();
    int qn = sQn;

    // Pipeline init: prefetch this warp's first queue entry BEFORE the fill
    // loop so the list-load latency overlaps the fill's store issue.
    int i = wid;
    int nGv = -1, nN = 0;
    int4 nP4 = make_int4(0, 0, 0, 0);
    if (i < qn) {
        int lv = sQ[i];
        nGv = vblock + lv;
        nN  = sCnt[lv];
        nP4 = *(const int4*)&d_list[(size_t)nGv * KMAX];
    }

    // Zero-fill this warp's 32 voxels in PAIRS. Both empty (~85%) -> one
    // STG.128 per lane covers both contiguous 256B voxel rows.
    {
        int kbase = wid << 5;
        float4 z4 = make_float4(0.f, 0.f, 0.f, 0.f);
        float2 z2 = make_float2(0.f, 0.f);
        #pragma unroll 4
        for (int k2 = 0; k2 < 16; k2++) {
            int v0 = kbase + (k2 << 1);
            int c0 = sCnt[v0], c1 = sCnt[v0 + 1];
            if ((c0 | c1) == 0) {
                ((float4*)(out + (size_t)(vblock + v0) * NCH))[lane] = z4;
            } else {
                if (c0 == 0) ((float2*)(out + (size_t)(vblock + v0) * NCH))[lane] = z2;
                if (c1 == 0) ((float2*)(out + (size_t)(vblock + v0 + 1) * NCH))[lane] = z2;
            }
        }
    }

    // Process non-empty entries; 2-deep pipeline hides list-load latency.
    while (nGv >= 0) {
        int gv = nGv, n = nN;
        int4 p4 = nP4;
        i += 8;
        if (i < qn) {
            int lv = sQ[i];
            nGv = vblock + lv;
            nN  = sCnt[lv];
            nP4 = *(const int4*)&d_list[(size_t)nGv * KMAX];   // prefetch next
        } else {
            nGv = -1;
        }

        float mx0 = -FLT_MAX, mx1 = -FLT_MAX;
        int mm = min(n, KMAX);
        {   // up to 4 independent feature-row loads (MLP), predicated
            float2 v0, v1, v2, v3;
            if (mm > 0) v0 = ((const float2*)(feat + (size_t)p4.x * NCH))[lane];
            if (mm > 1) v1 = ((const float2*)(feat + (size_t)p4.y * NCH))[lane];
            if (mm > 2) v2 = ((const float2*)(feat + (size_t)p4.z * NCH))[lane];
            if (mm > 3) v3 = ((const float2*)(feat + (size_t)p4.w * NCH))[lane];
            if (mm > 0) { mx0 = fmaxf(mx0, v0.x); mx1 = fmaxf(mx1, v0.y); }
            if (mm > 1) { mx0 = fmaxf(mx0, v1.x); mx1 = fmaxf(mx1, v1.y); }
            if (mm > 2) { mx0 = fmaxf(mx0, v2.x); mx1 = fmaxf(mx1, v2.y); }
            if (mm > 3) { mx0 = fmaxf(mx0, v3.x); mx1 = fmaxf(mx1, v3.y); }
        }
        const int* lst = &d_list[(size_t)gv * KMAX];
        for (int j = 4; j < mm; j++) {        // rare (P(n>4) tiny)
            int pid = lst[j];
            float2 v = ((const float2*)(feat + (size_t)pid * NCH))[lane];
            mx0 = fmaxf(mx0, v.x);
            mx1 = fmaxf(mx1, v.y);
        }

        if (n > KMAX) {
            // Correctness fallback (statistically never taken): rescan all
            // points. n is warp-uniform so the whole warp enters together.
            int r = gv / N_VOX, vox = gv % N_VOX;
            int xi = vox / (OUTD * OUTD), yi = (vox / OUTD) % OUTD, zi = vox % OUTD;
            const float* R = rois + r * 7;
            float cx = R[0], cy = R[1], cz = R[2];
            float dx = R[3], dy = R[4], dz = R[5];
            float ry = R[6];
            float hdx = dx * 0.5f, hdy = dy * 0.5f, hdz = dz * 0.5f;
            float ca = cosf(-ry), sa = sinf(-ry);
            float vx = dx / (float)OUTD, vy = dy / (float)OUTD, vz = dz / (float)OUTD;
            for (int bb = 0; bb < N_PTS; bb += 32) {
                int pp = bb + lane;
                bool hit = false;
                {
                    float sx = pts[3 * pp + 0] - cx;
                    float sy = pts[3 * pp + 1] - cy;
                    float szz = pts[3 * pp + 2] - cz;
                    float lx = sx * ca - sy * sa;
                    float ly = sx * sa + sy * ca;
                    if ((lx > -hdx) && (lx < hdx) && (ly > -hdy) && (ly < hdy) &&
                        (fabsf(szz - hdz) <= hdz)) {
                        int xa = min(OUTD - 1, max(0, (int)floorf((lx + hdx) / vx)));
                        int ya = min(OUTD - 1, max(0, (int)floorf((ly + hdy) / vy)));
                        int za = min(OUTD - 1, max(0, (int)floorf(szz / vz)));
                        hit = (xa == xi) && (ya == yi) && (za == zi);
                    }
                }
                unsigned mk = __ballot_sync(0xffffffffu, hit);
                while (mk) {
                    int src = __ffs(mk) - 1;
                    mk &= mk - 1;
                    int pid = bb + src;
                    float2 v = ((const float2*)(feat + (size_t)pid * NCH))[lane];
                    mx0 = fmaxf(mx0, v.x);
                    mx1 = fmaxf(mx1, v.y);
                }
            }
        }

        float2* o = (float2*)(out + (size_t)gv * NCH);
        o[lane] = make_float2(mx0, mx1);
    }
}

// ---------------------------------------------------------------------------
extern "C" void kernel_launch(void* const* d_in, const int* in_sizes, int n_in,
                              void* d_out, int out_size)
{
    const float* rois = (const float*)d_in[0];       // (128, 7)
    const float* pts  = (const float*)d_in[1];       // (160000, 3)
    const float* feat = (const float*)d_in[2];       // (160000, 64)
    float* out = (float*)d_out;                      // (128, 12, 12, 12, 64)

    build_lists_kernel<<<N_PTS / 256, 256>>>(rois, pts);    // R4 form (measured 9.7us)
    pool_kernel<<<NRV / 256, 256>>>(rois, pts, feat, out);  // 864 blocks, one wave
}

// round 8
// speedup vs baseline: 1.1800x; 1.1800x over previous
#include <cuda_runtime.h>
#include <math.h>
#include <float.h>

#define OUTD    12
#define N_VOX   1728              // 12*12*12
#define N_ROIS  128
#define N_PTS   160000
#define NCH     64
#define KMAX    64                // cap on points per (roi,voxel); fallback handles overflow
#define NRV     (N_ROIS * N_VOX)  // 221184 = 864 * 256
#define NF4     (NRV * NCH / 4)   // 3,538,944 float4s in output

static_assert(N_PTS % 256 == 0, "exact build grid");
static_assert(NRV % 256 == 0, "exact pool grid");
static_assert(NF4 % (256 * 8) == 0, "exact fill grid");

// Scratch (__device__ globals = sanctioned scratch; zero-initialized at load).
// d_count is self-cleaned by pool_kernel each run -> invariant holds across replays.
__device__ int d_count[NRV];
__device__ __align__(16) int d_list[NRV * KMAX];   // 16B align for int4 loads

// ---------------------------------------------------------------------------
// Side stream + events for overlapping the output zero-fill with build.
// Created once at load time (before the harness memory baseline); work done
// per call is identical every call. Fallback to serial if creation failed.
// ---------------------------------------------------------------------------
static cudaStream_t g_side = nullptr;
static cudaEvent_t  g_evFork = nullptr, g_evJoin = nullptr;
namespace {
struct SideInit {
    SideInit() {
        if (cudaStreamCreateWithFlags(&g_side, cudaStreamNonBlocking) != cudaSuccess)
            g_side = nullptr;
        if (cudaEventCreateWithFlags(&g_evFork, cudaEventDisableTiming) != cudaSuccess)
            g_evFork = nullptr;
        if (cudaEventCreateWithFlags(&g_evJoin, cudaEventDisableTiming) != cudaSuccess)
            g_evJoin = nullptr;
    }
};
static SideInit g_side_init;
}

// ---------------------------------------------------------------------------
// Kernel A: branchless zero-fill of the whole output. 1728 blocks x 256 thr,
// 8 contiguous STG.128 per thread (32KB/block), streaming (__stcs) to limit
// L2 pollution. Pure store bandwidth: overlaps build's pure-compute profile.
// ---------------------------------------------------------------------------
__global__ __launch_bounds__(256) void fill_kernel(float4* __restrict__ o4)
{
    int base = blockIdx.x * (256 * 8) + threadIdx.x;
    float4 z = make_float4(0.f, 0.f, 0.f, 0.f);
    #pragma unroll
    for (int k = 0; k < 8; k++)
        __stcs(&o4[base + k * 256], z);
}

// ---------------------------------------------------------------------------
// Kernel B: one thread per point, warp-uniform loop over all 128 ROIs
// (params staged in smem, broadcast LDS.128). R4 form exactly.
// ---------------------------------------------------------------------------
__global__ __launch_bounds__(256) void build_lists_kernel(
    const float* __restrict__ rois, const float* __restrict__ pts)
{
    __shared__ float4 sA[N_ROIS];  // {cx, cy, r2_margin, cz}
    __shared__ float4 sB[N_ROIS];  // {cosa, sina, hdx, hdy}
    __shared__ float4 sC[N_ROIS];  // {hdz, vx, vy, vz}

    int t = threadIdx.x;
    if (t < N_ROIS) {
        const float* R = rois + t * 7;
        float cx = R[0], cy = R[1], cz = R[2];
        float dx = R[3], dy = R[4], dz = R[5];
        float ry = R[6];
        float hdx = dx * 0.5f, hdy = dy * 0.5f, hdz = dz * 0.5f;
        float r2  = (hdx * hdx + hdy * hdy) * 1.0002f + 1e-6f;  // conservative
        float ca  = cosf(-ry), sa = sinf(-ry);
        sA[t] = make_float4(cx, cy, r2, cz);
        sB[t] = make_float4(ca, sa, hdx, hdy);
        sC[t] = make_float4(hdz, dx / (float)OUTD, dy / (float)OUTD, dz / (float)OUTD);
    }
    __syncthreads();

    int p = blockIdx.x * blockDim.x + t;      // always < N_PTS (exact grid)
    float px = pts[3 * p + 0];
    float py = pts[3 * p + 1];
    float pz = pts[3 * p + 2];

    #pragma unroll 4
    for (int r = 0; r < N_ROIS; r++) {
        float4 A = sA[r];                     // broadcast LDS.128 (uniform r)
        float sx = px - A.x;
        float sy = py - A.y;
        float d2 = sx * sx + sy * sy;
        if (d2 > A.z) continue;               // ~99.8% rejected here

        float sz = pz - A.w;
        float4 B = sB[r];
        float4 C = sC[r];
        float lx = sx * B.x - sy * B.y;       // rotate into roi frame (angle = -ry)
        float ly = sx * B.y + sy * B.x;
        bool in_box = (lx > -B.z) && (lx < B.z) &&
                      (ly > -B.w) && (ly < B.w) &&
                      (fabsf(sz - C.x) <= C.x);
        if (!in_box) continue;

        int xi = min(OUTD - 1, max(0, (int)floorf((lx + B.z) / C.y)));
        int yi = min(OUTD - 1, max(0, (int)floorf((ly + B.w) / C.z)));
        int zi = min(OUTD - 1, max(0, (int)floorf(sz / C.w)));
        int rv = r * N_VOX + xi * (OUTD * OUTD) + yi * OUTD + zi;
        int c = atomicAdd(&d_count[rv], 1);
        if (c < KMAX) d_list[rv * KMAX + c] = p;
    }
}

// ---------------------------------------------------------------------------
// Kernel C: gather-only pool (R5 measured-best form). Block = 256 voxels,
// __launch_bounds__(256,6) -> single wave. Coalesced count scan + self-clean,
// ballot-compaction of non-empty voxels (~19/block), 2-deep pipeline over
// queue entries. Empty voxels: nothing (fill_kernel wrote them).
// ---------------------------------------------------------------------------
__global__ __launch_bounds__(256, 6) void pool_kernel(
    const float* __restrict__ rois, const float* __restrict__ pts,
    const float* __restrict__ feat, float* __restrict__ out)
{
    __shared__ int sCnt[256];
    __shared__ int sQ[256];
    __shared__ int sQn;

    int t    = threadIdx.x;
    int lane = t & 31;
    int wid  = t >> 5;
    int vblock = blockIdx.x << 8;             // first voxel of this block

    int c = d_count[vblock + t];              // coalesced 1KB burst
    sCnt[t] = c;
    if (c) d_count[vblock + t] = 0;           // self-clean only dirty entries
    if (t == 0) sQn = 0;
    __syncthreads();

    // Ballot-compact non-empty local voxel ids into sQ.
    unsigned m = __ballot_sync(0xffffffffu, c > 0);
    int base = 0;
    if (lane == 0 && m) base = atomicAdd(&sQn, __popc(m));
    base = __shfl_sync(0xffffffffu, base, 0);
    if (c > 0) sQ[base + __popc(m & ((1u << lane) - 1u))] = t;
    __syncthreads();
    int qn = sQn;

    // Warps grab entries strided; 2-deep pipeline hides list-load latency.
    int i = wid;
    int nGv = -1, nN = 0;
    int4 nP4 = make_int4(0, 0, 0, 0);
    if (i < qn) {
        int lv = sQ[i];
        nGv = vblock + lv;
        nN  = sCnt[lv];
        nP4 = *(const int4*)&d_list[(size_t)nGv * KMAX];
    }
    while (nGv >= 0) {
        int gv = nGv, n = nN;
        int4 p4 = nP4;
        i += 8;
        if (i < qn) {
            int lv = sQ[i];
            nGv = vblock + lv;
            nN  = sCnt[lv];
            nP4 = *(const int4*)&d_list[(size_t)nGv * KMAX];   // prefetch next
        } else {
            nGv = -1;
        }

        float mx0 = -FLT_MAX, mx1 = -FLT_MAX;
        int mm = min(n, KMAX);
        {   // up to 4 independent feature-row loads (MLP), predicated
            float2 v0, v1, v2, v3;
            if (mm > 0) v0 = ((const float2*)(feat + (size_t)p4.x * NCH))[lane];
            if (mm > 1) v1 = ((const float2*)(feat + (size_t)p4.y * NCH))[lane];
            if (mm > 2) v2 = ((const float2*)(feat + (size_t)p4.z * NCH))[lane];
            if (mm > 3) v3 = ((const float2*)(feat + (size_t)p4.w * NCH))[lane];
            if (mm > 0) { mx0 = fmaxf(mx0, v0.x); mx1 = fmaxf(mx1, v0.y); }
            if (mm > 1) { mx0 = fmaxf(mx0, v1.x); mx1 = fmaxf(mx1, v1.y); }
            if (mm > 2) { mx0 = fmaxf(mx0, v2.x); mx1 = fmaxf(mx1, v2.y); }
            if (mm > 3) { mx0 = fmaxf(mx0, v3.x); mx1 = fmaxf(mx1, v3.y); }
        }
        const int* lst = &d_list[(size_t)gv * KMAX];
        for (int j = 4; j < mm; j++) {        // rare (P(n>4) tiny)
            int pid = lst[j];
            float2 v = ((const float2*)(feat + (size_t)pid * NCH))[lane];
            mx0 = fmaxf(mx0, v.x);
            mx1 = fmaxf(mx1, v.y);
        }

        if (n > KMAX) {
            // Correctness fallback (statistically never taken): rescan all
            // points. n is warp-uniform so the whole warp enters together.
            int r = gv / N_VOX, vox = gv % N_VOX;
            int xi = vox / (OUTD * OUTD), yi = (vox / OUTD) % OUTD, zi = vox % OUTD;
            const float* R = rois + r * 7;
            float cx = R[0], cy = R[1], cz = R[2];
            float dx = R[3], dy = R[4], dz = R[5];
            float ry = R[6];
            float hdx = dx * 0.5f, hdy = dy * 0.5f, hdz = dz * 0.5f;
            float ca = cosf(-ry), sa = sinf(-ry);
            float vx = dx / (float)OUTD, vy = dy / (float)OUTD, vz = dz / (float)OUTD;
            for (int bb = 0; bb < N_PTS; bb += 32) {
                int pp = bb + lane;
                bool hit = false;
                {
                    float sx = pts[3 * pp + 0] - cx;
                    float sy = pts[3 * pp + 1] - cy;
                    float szz = pts[3 * pp + 2] - cz;
                    float lx = sx * ca - sy * sa;
                    float ly = sx * sa + sy * ca;
                    if ((lx > -hdx) && (lx < hdx) && (ly > -hdy) && (ly < hdy) &&
                        (fabsf(szz - hdz) <= hdz)) {
                        int xa = min(OUTD - 1, max(0, (int)floorf((lx + hdx) / vx)));
                        int ya = min(OUTD - 1, max(0, (int)floorf((ly + hdy) / vy)));
                        int za = min(OUTD - 1, max(0, (int)floorf(szz / vz)));
                        hit = (xa == xi) && (ya == yi) && (za == zi);
                    }
                }
                unsigned mk = __ballot_sync(0xffffffffu, hit);
                while (mk) {
                    int src = __ffs(mk) - 1;
                    mk &= mk - 1;
                    int pid = bb + src;
                    float2 v = ((const float2*)(feat + (size_t)pid * NCH))[lane];
                    mx0 = fmaxf(mx0, v.x);
                    mx1 = fmaxf(mx1, v.y);
                }
            }
        }

        float2* o = (float2*)(out + (size_t)gv * NCH);
        __stcs(&o[lane], make_float2(mx0, mx1));
    }
}

// ---------------------------------------------------------------------------
extern "C" void kernel_launch(void* const* d_in, const int* in_sizes, int n_in,
                              void* d_out, int out_size)
{
    const float* rois = (const float*)d_in[0];       // (128, 7)
    const float* pts  = (const float*)d_in[1];       // (160000, 3)
    const float* feat = (const float*)d_in[2];       // (160000, 64)
    float* out = (float*)d_out;                      // (128, 12, 12, 12, 64)

    if (g_side && g_evFork && g_evJoin) {
        // Fork: fill runs on the side stream, overlapping build on the main
        // stream (disjoint resources: LTS stores vs issue/ALU). Join before
        // pool, which overwrites non-empty voxels.
        cudaEventRecord(g_evFork, 0);
        cudaStreamWaitEvent(g_side, g_evFork, 0);
        fill_kernel<<<NF4 / (256 * 8), 256, 0, g_side>>>((float4*)out);
        cudaEventRecord(g_evJoin, g_side);
        build_lists_kernel<<<N_PTS / 256, 256>>>(rois, pts);
        cudaStreamWaitEvent(0, g_evJoin, 0);
    } else {
        // Serial fallback (stream/event creation failed).
        fill_kernel<<<NF4 / (256 * 8), 256>>>((float4*)out);
        build_lists_kernel<<<N_PTS / 256, 256>>>(rois, pts);
    }
    pool_kernel<<<NRV / 256, 256>>>(rois, pts, feat, out);
}

// round 9
// speedup vs baseline: 1.4143x; 1.1985x over previous
#include <cuda_runtime.h>
#include <math.h>
#include <float.h>

#define OUTD    12
#define N_VOX   1728              // 12*12*12
#define N_ROIS  128
#define N_PTS   160000
#define NCH     64
#define KMAX    64                // cap on points per (roi,voxel); fallback handles overflow
#define NRV     (N_ROIS * N_VOX)  // 221184
#define NF4     (NRV * NCH / 4)   // 3,538,944 float4s in output

#define POOL_BLOCKS 888           // 148 SMs x 6 blocks -> single wave
#define POOL_WARPS  (POOL_BLOCKS * 8)

static_assert(N_PTS % 256 == 0, "exact build grid");
static_assert(NF4 % (256 * 8) == 0, "exact fill grid");

// Scratch (__device__ globals = sanctioned scratch; zero-initialized at load).
// Invariants restored every run: d_count zeroed by pool, d_qn zeroed by fill.
__device__ int d_count[NRV];
__device__ __align__(16) int d_list[NRV * KMAX];   // 16B align for int4 loads
__device__ int d_qn;
__device__ int d_queue[NRV];

// ---------------------------------------------------------------------------
// Kernel A: zero-fill whole output (pool overwrites non-empty voxels later).
// Also resets the worklist counter (kernel-boundary orders it before build).
// ---------------------------------------------------------------------------
__global__ __launch_bounds__(256) void fill_kernel(float4* __restrict__ o4)
{
    if (blockIdx.x == 0 && threadIdx.x == 0) d_qn = 0;
    int base = blockIdx.x * (256 * 8) + threadIdx.x;
    float4 z = make_float4(0.f, 0.f, 0.f, 0.f);
    #pragma unroll
    for (int k = 0; k < 8; k++)
        __stcs(&o4[base + k * 256], z);
}

// ---------------------------------------------------------------------------
// Kernel B: one thread per point, warp-uniform loop over all 128 ROIs
// (params staged in smem, broadcast LDS.128). First inserter of each voxel
// (atomicAdd returned 0) pushes rv onto the global worklist -> pool needs
// no count scan. ~17K pushes total: negligible.
// ---------------------------------------------------------------------------
__global__ __launch_bounds__(256) void build_lists_kernel(
    const float* __restrict__ rois, const float* __restrict__ pts)
{
    __shared__ float4 sA[N_ROIS];  // {cx, cy, r2_margin, cz}
    __shared__ float4 sB[N_ROIS];  // {cosa, sina, hdx, hdy}
    __shared__ float4 sC[N_ROIS];  // {hdz, vx, vy, vz}

    int t = threadIdx.x;
    if (t < N_ROIS) {
        const float* R = rois + t * 7;
        float cx = R[0], cy = R[1], cz = R[2];
        float dx = R[3], dy = R[4], dz = R[5];
        float ry = R[6];
        float hdx = dx * 0.5f, hdy = dy * 0.5f, hdz = dz * 0.5f;
        float r2  = (hdx * hdx + hdy * hdy) * 1.0002f + 1e-6f;  // conservative
        float ca  = cosf(-ry), sa = sinf(-ry);
        sA[t] = make_float4(cx, cy, r2, cz);
        sB[t] = make_float4(ca, sa, hdx, hdy);
        sC[t] = make_float4(hdz, dx / (float)OUTD, dy / (float)OUTD, dz / (float)OUTD);
    }
    __syncthreads();

    int p = blockIdx.x * blockDim.x + t;      // always < N_PTS (exact grid)
    float px = pts[3 * p + 0];
    float py = pts[3 * p + 1];
    float pz = pts[3 * p + 2];

    #pragma unroll 4
    for (int r = 0; r < N_ROIS; r++) {
        float4 A = sA[r];                     // broadcast LDS.128 (uniform r)
        float sx = px - A.x;
        float sy = py - A.y;
        float d2 = sx * sx + sy * sy;
        if (d2 > A.z) continue;               // ~99.8% rejected here

        float sz = pz - A.w;
        float4 B = sB[r];
        float4 C = sC[r];
        float lx = sx * B.x - sy * B.y;       // rotate into roi frame (angle = -ry)
        float ly = sx * B.y + sy * B.x;
        bool in_box = (lx > -B.z) && (lx < B.z) &&
                      (ly > -B.w) && (ly < B.w) &&
                      (fabsf(sz - C.x) <= C.x);
        if (!in_box) continue;

        int xi = min(OUTD - 1, max(0, (int)floorf((lx + B.z) / C.y)));
        int yi = min(OUTD - 1, max(0, (int)floorf((ly + B.w) / C.z)));
        int zi = min(OUTD - 1, max(0, (int)floorf(sz / C.w)));
        int rv = r * N_VOX + xi * (OUTD * OUTD) + yi * OUTD + zi;
        int c = atomicAdd(&d_count[rv], 1);
        if (c < KMAX) d_list[rv * KMAX + c] = p;
        if (c == 0) {                         // unique first inserter
            int qi = atomicAdd(&d_qn, 1);
            d_queue[qi] = rv;
        }
    }
}

// ---------------------------------------------------------------------------
// Kernel C: worklist pool. Single wave (888 blocks); warps grid-stride over
// the ~17K queue entries (~2.4/warp). Per entry: rv -> (count, pid int4) ->
// up to 4 independent feature rows -> 256B output store. 2-deep pipeline
// prefetches the next entry's whole chain. Counts self-cleaned per entry.
// ---------------------------------------------------------------------------
__global__ __launch_bounds__(256, 6) void pool_kernel(
    const float* __restrict__ rois, const float* __restrict__ pts,
    const float* __restrict__ feat, float* __restrict__ out)
{
    int lane  = threadIdx.x & 31;
    int gwarp = blockIdx.x * 8 + (threadIdx.x >> 5);
    int qn    = d_qn;                          // L2-hot, uniform

    // Pipeline init: prefetch first entry's chain.
    int i = gwarp;
    int nRv = -1, nN = 0;
    int4 nP4 = make_int4(0, 0, 0, 0);
    if (i < qn) {
        nRv = d_queue[i];
        nN  = d_count[nRv];
        nP4 = *(const int4*)&d_list[(size_t)nRv * KMAX];
    }

    while (nRv >= 0) {
        int rv = nRv, n = nN;
        int4 p4 = nP4;
        if (lane == 0) d_count[rv] = 0;        // self-clean for next replay
        i += POOL_WARPS;
        if (i < qn) {
            nRv = d_queue[i];
            nN  = d_count[nRv];
            nP4 = *(const int4*)&d_list[(size_t)nRv * KMAX];   // prefetch next
        } else {
            nRv = -1;
        }

        float mx0 = -FLT_MAX, mx1 = -FLT_MAX;
        int mm = min(n, KMAX);
        {   // up to 4 independent feature-row loads (MLP), predicated
            float2 v0, v1, v2, v3;
            if (mm > 0) v0 = ((const float2*)(feat + (size_t)p4.x * NCH))[lane];
            if (mm > 1) v1 = ((const float2*)(feat + (size_t)p4.y * NCH))[lane];
            if (mm > 2) v2 = ((const float2*)(feat + (size_t)p4.z * NCH))[lane];
            if (mm > 3) v3 = ((const float2*)(feat + (size_t)p4.w * NCH))[lane];
            if (mm > 0) { mx0 = fmaxf(mx0, v0.x); mx1 = fmaxf(mx1, v0.y); }
            if (mm > 1) { mx0 = fmaxf(mx0, v1.x); mx1 = fmaxf(mx1, v1.y); }
            if (mm > 2) { mx0 = fmaxf(mx0, v2.x); mx1 = fmaxf(mx1, v2.y); }
            if (mm > 3) { mx0 = fmaxf(mx0, v3.x); mx1 = fmaxf(mx1, v3.y); }
        }
        const int* lst = &d_list[(size_t)rv * KMAX];
        for (int j = 4; j < mm; j++) {         // rare (P(n>4) tiny)
            int pid = lst[j];
            float2 v = ((const float2*)(feat + (size_t)pid * NCH))[lane];
            mx0 = fmaxf(mx0, v.x);
            mx1 = fmaxf(mx1, v.y);
        }

        if (n > KMAX) {
            // Correctness fallback (statistically never taken): rescan all
            // points. n is warp-uniform so the whole warp enters together.
            int r = rv / N_VOX, vox = rv % N_VOX;
            int xi = vox / (OUTD * OUTD), yi = (vox / OUTD) % OUTD, zi = vox % OUTD;
            const float* R = rois + r * 7;
            float cx = R[0], cy = R[1], cz = R[2];
            float dx = R[3], dy = R[4], dz = R[5];
            float ry = R[6];
            float hdx = dx * 0.5f, hdy = dy * 0.5f, hdz = dz * 0.5f;
            float ca = cosf(-ry), sa = sinf(-ry);
            float vx = dx / (float)OUTD, vy = dy / (float)OUTD, vz = dz / (float)OUTD;
            for (int bb = 0; bb < N_PTS; bb += 32) {
                int pp = bb + lane;
                bool hit = false;
                {
                    float sx = pts[3 * pp + 0] - cx;
                    float sy = pts[3 * pp + 1] - cy;
                    float szz = pts[3 * pp + 2] - cz;
                    float lx = sx * ca - sy * sa;
                    float ly = sx * sa + sy * ca;
                    if ((lx > -hdx) && (lx < hdx) && (ly > -hdy) && (ly < hdy) &&
                        (fabsf(szz - hdz) <= hdz)) {
                        int xa = min(OUTD - 1, max(0, (int)floorf((lx + hdx) / vx)));
                        int ya = min(OUTD - 1, max(0, (int)floorf((ly + hdy) / vy)));
                        int za = min(OUTD - 1, max(0, (int)floorf(szz / vz)));
                        hit = (xa == xi) && (ya == yi) && (za == zi);
                    }
                }
                unsigned mk = __ballot_sync(0xffffffffu, hit);
                while (mk) {
                    int src = __ffs(mk) - 1;
                    mk &= mk - 1;
                    int pid = bb + src;
                    float2 v = ((const float2*)(feat + (size_t)pid * NCH))[lane];
                    mx0 = fmaxf(mx0, v.x);
                    mx1 = fmaxf(mx1, v.y);
                }
            }
        }

        float2* o = (float2*)(out + (size_t)rv * NCH);
        __stcs(&o[lane], make_float2(mx0, mx1));
    }
}

// ---------------------------------------------------------------------------
extern "C" void kernel_launch(void* const* d_in, const int* in_sizes, int n_in,
                              void* d_out, int out_size)
{
    const float* rois = (const float*)d_in[0];       // (128, 7)
    const float* pts  = (const float*)d_in[1];       // (160000, 3)
    const float* feat = (const float*)d_in[2];       // (160000, 64)
    float* out = (float*)d_out;                      // (128, 12, 12, 12, 64)

    fill_kernel<<<NF4 / (256 * 8), 256>>>((float4*)out);     // zeros + d_qn reset
    build_lists_kernel<<<N_PTS / 256, 256>>>(rois, pts);     // lists + worklist
    pool_kernel<<<POOL_BLOCKS, 256>>>(rois, pts, feat, out); // worklist gather
}